// round 16
// baseline (speedup 1.0000x reference)
#include <cuda_runtime.h>
#include <cuda_fp16.h>
#include <cstdint>

// Problem constants (fixed by the reference).
#define NNODES 50000
#define ETOT   850000      // E (800000) + N self loops
#define GG     256
#define INCH   64
#define HEADS  8
#define CH     16
#define DH     128
#define NWP    160         // permuted row: 8 groups * 20 slots (18 used + 2 pad)
#define NEG_SLOPE 0.2f
#define MAXDEG 64          // in-degree is Poisson(17); P(>63) ~ 1e-12
#define LOG2E 1.4426950408889634f

#define BM 128
#define BK 16
#define XS_STRIDE 20
#define WS_STRIDE 168

#define WTF_OFF1 0
#define WTF_OFF2 (INCH * NWP)
#define WTF_OFF3 (WTF_OFF2 + DH * NWP)
#define WTF_TOTAL (WTF_OFF3 + DH * NWP)

// ---------------------------------------------------------------------------
// Scratch (__device__ globals; no allocations allowed).
// ---------------------------------------------------------------------------
__device__ __align__(128) uint32_t g_hh  [NNODES * (DH / 2)];  // h as half2
__device__ __align__(128) float    g_bufA[NNODES * DH];
__device__ __align__(128) float    g_bufB[NNODES * DH];
__device__ __align__(16)  float    g_asrc[NNODES * HEADS];
__device__ __align__(16)  float    g_adst[NNODES * HEADS];
__device__ __align__(128) uint32_t g_wtf [WTF_TOTAL];
__device__ __align__(128) float    g_pool[GG * DH];
__device__ int g_cnt [NNODES];
__device__ int g_csrc[NNODES * MAXDEG];

// ---------------------------------------------------------------------------
__device__ __forceinline__ float lrelu(float v) {
    return fmaxf(v, NEG_SLOPE * v);
}
__device__ __forceinline__ float* out_buf(int sel) { return sel == 1 ? g_bufA : g_bufB; }

__device__ __forceinline__ void red_add_v4(float* p, float a, float b, float c, float d) {
    asm volatile("red.global.add.v4.f32 [%0], {%1, %2, %3, %4};"
                 :: "l"(p), "f"(a), "f"(b), "f"(c), "f"(d) : "memory");
}

__device__ __forceinline__ uint32_t f2tf32(float f) {
    uint32_t r;
    asm("cvt.rna.tf32.f32 %0, %1;" : "=r"(r) : "f"(f));
    return r;
}

__device__ __forceinline__ uint32_t smem_u32(const void* p) {
    return (uint32_t)__cvta_generic_to_shared(p);
}

__device__ __forceinline__ void cp_async16(uint32_t dst, const void* src, int src_sz) {
    asm volatile("cp.async.ca.shared.global [%0], [%1], 16, %2;"
                 :: "r"(dst), "l"(src), "r"(src_sz));
}
__device__ __forceinline__ void cp_commit() {
    asm volatile("cp.async.commit_group;");
}
template <int N>
__device__ __forceinline__ void cp_wait() {
    asm volatile("cp.async.wait_group %0;" :: "n"(N));
}

__device__ __forceinline__ void mma_tf32(float* c,
                                         uint32_t a0, uint32_t a1, uint32_t a2, uint32_t a3,
                                         uint32_t b0, uint32_t b1)
{
    asm("mma.sync.aligned.m16n8k8.row.col.f32.tf32.tf32.f32 "
        "{%0,%1,%2,%3}, {%4,%5,%6,%7}, {%8,%9}, {%0,%1,%2,%3};"
        : "+f"(c[0]), "+f"(c[1]), "+f"(c[2]), "+f"(c[3])
        : "r"(a0), "r"(a1), "r"(a2), "r"(a3), "r"(b0), "r"(b1));
}

// ===========================================================================
// Padded-CSR build + pool zero.
// ===========================================================================
__global__ void init_kernel()
{
    int i = blockIdx.x * blockDim.x + threadIdx.x;
    if (i < NNODES) g_cnt[i] = 0;
    if (i < GG * DH) g_pool[i] = 0.0f;
}

__global__ void fill_kernel(const int* __restrict__ src, const int* __restrict__ dst)
{
    int e = blockIdx.x * blockDim.x + threadIdx.x;
    if (e >= ETOT) return;
    int d = __ldg(&dst[e]);
    int pos = atomicAdd(&g_cnt[d], 1);
    if (pos < MAXDEG) g_csrc[d * MAXDEG + pos] = __ldg(&src[e]);
}

// ===========================================================================
// Prep: fused tf32 weights [W | Wa_src | Wa_dst], permuted; alpha cols
// pre-scaled by log2(e) so gather uses exp2f.
// ===========================================================================
__global__ void prep_kernel(const float* __restrict__ W1, const float* __restrict__ as1, const float* __restrict__ ad1,
                            const float* __restrict__ W2, const float* __restrict__ as2, const float* __restrict__ ad2,
                            const float* __restrict__ W3, const float* __restrict__ as3, const float* __restrict__ ad3)
{
    int idx = blockIdx.x * blockDim.x + threadIdx.x;
    if (idx >= WTF_TOTAL) return;

    const float *W, *as, *ad;
    int li;
    if (idx < WTF_OFF2)      { W = W1; as = as1; ad = ad1; li = idx - WTF_OFF1; }
    else if (idx < WTF_OFF3) { W = W2; as = as2; ad = ad2; li = idx - WTF_OFF2; }
    else                     { W = W3; as = as3; ad = ad3; li = idx - WTF_OFF3; }

    int k  = li / NWP;
    int p  = li - k * NWP;
    int qr = p / 20;
    int nt = p - qr * 20;
    if (nt >= 18) { g_wtf[idx] = 0; return; }
    int n = nt * 8 + qr;

    float v;
    if (n < DH) {
        v = __ldg(&W[k * DH + n]);
    } else if (n < DH + HEADS) {
        int hh = n - DH;
        float s = 0.0f;
#pragma unroll
        for (int c = 0; c < CH; ++c)
            s += __ldg(&W[k * DH + hh * CH + c]) * __ldg(&as[hh * CH + c]);
        v = s * LOG2E;
    } else {
        int hh = n - DH - HEADS;
        float s = 0.0f;
#pragma unroll
        for (int c = 0; c < CH; ++c)
            s += __ldg(&W[k * DH + hh * CH + c]) * __ldg(&ad[hh * CH + c]);
        v = s * LOG2E;
    }
    g_wtf[idx] = f2tf32(v);
}

// ===========================================================================
// Node phase (tensor cores): [h | asrc | adst] = xin @ [W|Was|Wad]
// h written as half2 (gather reads fp16); alphas fp32.
// ===========================================================================
template <int K>
__global__ void __launch_bounds__(256) gemm_alpha_tc(const float* __restrict__ xext, int in_sel,
                                                     int wtf_off)
{
    const float* __restrict__ xin =
        (in_sel == 0) ? xext : (in_sel == 1 ? (const float*)g_bufA : (const float*)g_bufB);
    const uint32_t* __restrict__ wtf = g_wtf + wtf_off;

    __shared__ float    xs[2][BM][XS_STRIDE];
    __shared__ uint32_t ws[2][BK][WS_STRIDE];

    const int t    = threadIdx.x;
    const int wid  = t >> 5;
    const int lid  = t & 31;
    const int row0 = blockIdx.x * BM;
    const int qr   = lid >> 2;
    const int qc   = lid & 3;

    float c[18][4];
#pragma unroll
    for (int nt = 0; nt < 18; ++nt)
#pragma unroll
        for (int j = 0; j < 4; ++j) c[nt][j] = 0.0f;

    auto load_tiles = [&](int buf, int k0) {
#pragma unroll
        for (int i = 0; i < 2; ++i) {
            int idx = t + i * 256;
            int r   = idx >> 2;
            int c4  = idx & 3;
            int row = row0 + r;
            const float* src = &xin[(long)row * K + k0 + c4 * 4];
            int sz = (row < NNODES) ? 16 : 0;
            cp_async16(smem_u32(&xs[buf][r][c4 * 4]), src, sz);
        }
#pragma unroll
        for (int i = 0; i < 3; ++i) {
            int idx = t + i * 256;
            if (idx < 640) {
                int r  = idx / 40;
                int c4 = idx - r * 40;
                cp_async16(smem_u32(&ws[buf][r][c4 * 4]), &wtf[(k0 + r) * NWP + c4 * 4], 16);
            }
        }
    };

    load_tiles(0, 0);
    cp_commit();

    const int NK = K / BK;
    for (int kt = 0; kt < NK; ++kt) {
        const int buf = kt & 1;
        if (kt + 1 < NK) {
            load_tiles(buf ^ 1, (kt + 1) * BK);
            cp_commit();
            cp_wait<1>();
        } else {
            cp_wait<0>();
        }
        __syncthreads();

        const int r0 = wid * 16;
#pragma unroll
        for (int ks = 0; ks < BK; ks += 8) {
            uint32_t a0 = f2tf32(xs[buf][r0 + qr    ][ks + qc]);
            uint32_t a1 = f2tf32(xs[buf][r0 + qr + 8][ks + qc]);
            uint32_t a2 = f2tf32(xs[buf][r0 + qr    ][ks + qc + 4]);
            uint32_t a3 = f2tf32(xs[buf][r0 + qr + 8][ks + qc + 4]);

            const uint32_t* brow0 = &ws[buf][ks + qc    ][qr * 20];
            const uint32_t* brow1 = &ws[buf][ks + qc + 4][qr * 20];
#pragma unroll
            for (int ch = 0; ch < 4; ++ch) {
                uint4 b0 = *(const uint4*)&brow0[ch * 4];
                uint4 b1 = *(const uint4*)&brow1[ch * 4];
                mma_tf32(c[ch * 4 + 0], a0, a1, a2, a3, b0.x, b1.x);
                mma_tf32(c[ch * 4 + 1], a0, a1, a2, a3, b0.y, b1.y);
                mma_tf32(c[ch * 4 + 2], a0, a1, a2, a3, b0.z, b1.z);
                mma_tf32(c[ch * 4 + 3], a0, a1, a2, a3, b0.w, b1.w);
            }
            {
                uint2 b0 = *(const uint2*)&brow0[16];
                uint2 b1 = *(const uint2*)&brow1[16];
                mma_tf32(c[16], a0, a1, a2, a3, b0.x, b1.x);
                mma_tf32(c[17], a0, a1, a2, a3, b0.y, b1.y);
            }
        }
        __syncthreads();
    }

    const int r0   = wid * 16;
    const int row1 = row0 + r0 + qr;
    const int row2 = row1 + 8;
    const bool ok1 = row1 < NNODES;
    const bool ok2 = row2 < NNODES;

    // h stored as half2: col pair (nt*8+qc*2, +1) -> half2 index nt*4+qc
#pragma unroll
    for (int nt = 0; nt < 16; ++nt) {
        int hidx = nt * 4 + qc;
        if (ok1) {
            half2 hv = __float22half2_rn(make_float2(c[nt][0], c[nt][1]));
            g_hh[row1 * (DH / 2) + hidx] = *(uint32_t*)&hv;
        }
        if (ok2) {
            half2 hv = __float22half2_rn(make_float2(c[nt][2], c[nt][3]));
            g_hh[row2 * (DH / 2) + hidx] = *(uint32_t*)&hv;
        }
    }
    {
        int hh = qc * 2;
        if (ok1) *(float2*)&g_asrc[row1 * HEADS + hh] = make_float2(c[16][0], c[16][1]);
        if (ok2) *(float2*)&g_asrc[row2 * HEADS + hh] = make_float2(c[16][2], c[16][3]);
        if (ok1) *(float2*)&g_adst[row1 * HEADS + hh] = make_float2(c[17][0], c[17][1]);
        if (ok2) *(float2*)&g_adst[row2 * HEADS + hh] = make_float2(c[17][2], c[17][3]);
    }
}

// ===========================================================================
// Fused edge kernel. Warp per dst node; 16 lanes per edge (2 edges in
// parallel across the warp); lane owns 8 halfs (one uint4) of the row.
// Fast path (cnt <= 32, ~99.98% of nodes): 8-edge inner batch -> 8
// outstanding loads per thread for latency hiding.
// ===========================================================================
__device__ __forceinline__ void acc8(float4& lo, float4& hi, const uint4& hv, float w)
{
    float2 f0 = __half22float2(*(const half2*)&hv.x);
    float2 f1 = __half22float2(*(const half2*)&hv.y);
    float2 f2 = __half22float2(*(const half2*)&hv.z);
    float2 f3 = __half22float2(*(const half2*)&hv.w);
    lo.x = fmaf(w, f0.x, lo.x); lo.y = fmaf(w, f0.y, lo.y);
    lo.z = fmaf(w, f1.x, lo.z); lo.w = fmaf(w, f1.y, lo.w);
    hi.x = fmaf(w, f2.x, hi.x); hi.y = fmaf(w, f2.y, hi.y);
    hi.z = fmaf(w, f3.x, hi.z); hi.w = fmaf(w, f3.y, hi.w);
}

__global__ void __launch_bounds__(256) gat_gather_kernel(int out_sel,
                                                         const float* __restrict__ bias,
                                                         const int* __restrict__ batch,
                                                         int do_pool)
{
    float* __restrict__ xout = out_buf(out_sel);
    const int lane = threadIdx.x & 31;
    const int d = blockIdx.x * (blockDim.x >> 5) + (threadIdx.x >> 5);
    if (d >= NNODES) return;

    const int half_id = lane >> 4;
    const int l16     = lane & 15;
    const int hh      = l16 >> 1;
    const int cnt     = __ldg(&g_cnt[d]);
    const int base    = d * MAXDEG;

    const float adc = __ldg(&g_adst[d * HEADS + hh]);

    // coalesced edge-list load, distributed by shuffle
    int sv0 = 0, sv1 = 0;
    if (lane < cnt)      sv0 = __ldg(&g_csrc[base + lane]);
    if (lane + 32 < cnt) sv1 = __ldg(&g_csrc[base + lane + 32]);

    float sA = 0.0f, sB = 0.0f;
    float4 lo = make_float4(0.f, 0.f, 0.f, 0.f);
    float4 hi = make_float4(0.f, 0.f, 0.f, 0.f);
    const uint4* __restrict__ h8 = (const uint4*)g_hh;   // 16 uint4 per row

    int i = 0;
    if (cnt <= 32) {
        // -------- fast path: all indices in sv0; 8-edge batches --------
        for (; i + 8 <= cnt; i += 8) {
            int s0 = __shfl_sync(0xffffffffu, sv0, i     + half_id);
            int s1 = __shfl_sync(0xffffffffu, sv0, i + 2 + half_id);
            int s2 = __shfl_sync(0xffffffffu, sv0, i + 4 + half_id);
            int s3 = __shfl_sync(0xffffffffu, sv0, i + 6 + half_id);
            // issue all 8 loads before any consumption
            float as0 = __ldg(&g_asrc[s0 * HEADS + hh]);
            float as1 = __ldg(&g_asrc[s1 * HEADS + hh]);
            float as2 = __ldg(&g_asrc[s2 * HEADS + hh]);
            float as3 = __ldg(&g_asrc[s3 * HEADS + hh]);
            uint4 hv0 = __ldg(&h8[s0 * 16 + l16]);
            uint4 hv1 = __ldg(&h8[s1 * 16 + l16]);
            uint4 hv2 = __ldg(&h8[s2 * 16 + l16]);
            uint4 hv3 = __ldg(&h8[s3 * 16 + l16]);

            float w0 = exp2f(lrelu(as0 + adc));
            float w1 = exp2f(lrelu(as1 + adc));
            float w2 = exp2f(lrelu(as2 + adc));
            float w3 = exp2f(lrelu(as3 + adc));
            sA += w0 + w1;
            sB += w2 + w3;
            acc8(lo, hi, hv0, w0);
            acc8(lo, hi, hv1, w1);
            acc8(lo, hi, hv2, w2);
            acc8(lo, hi, hv3, w3);
        }
        for (; i < cnt; i += 2) {
            int j = i + half_id;
            bool valid = j < cnt;
            int jj = valid ? j : (cnt - 1);
            int s = __shfl_sync(0xffffffffu, sv0, jj);
            float as = __ldg(&g_asrc[s * HEADS + hh]);
            uint4 hv = __ldg(&h8[s * 16 + l16]);
            float w = valid ? exp2f(lrelu(as + adc)) : 0.0f;
            sA += w;
            acc8(lo, hi, hv, w);
        }
    } else {
        // -------- rare path: cnt in (32, 64] --------
        for (; i < cnt; i += 2) {
            int j = i + half_id;
            bool valid = j < cnt;
            int jj = valid ? j : (cnt - 1);
            int a = __shfl_sync(0xffffffffu, sv0, jj & 31);
            int b = __shfl_sync(0xffffffffu, sv1, jj & 31);
            int s = (jj < 32) ? a : b;
            float as = __ldg(&g_asrc[s * HEADS + hh]);
            uint4 hv = __ldg(&h8[s * 16 + l16]);
            float w = valid ? exp2f(lrelu(as + adc)) : 0.0f;
            sA += w;
            acc8(lo, hi, hv, w);
        }
    }

    // combine the two half-warps
    float sT = sA + sB;
    sT  += __shfl_xor_sync(0xffffffffu, sT, 16);
    lo.x += __shfl_xor_sync(0xffffffffu, lo.x, 16);
    lo.y += __shfl_xor_sync(0xffffffffu, lo.y, 16);
    lo.z += __shfl_xor_sync(0xffffffffu, lo.z, 16);
    lo.w += __shfl_xor_sync(0xffffffffu, lo.w, 16);
    hi.x += __shfl_xor_sync(0xffffffffu, hi.x, 16);
    hi.y += __shfl_xor_sync(0xffffffffu, hi.y, 16);
    hi.z += __shfl_xor_sync(0xffffffffu, hi.z, 16);
    hi.w += __shfl_xor_sync(0xffffffffu, hi.w, 16);

    if (half_id == 0) {
        const float inv = 1.0f / sT;
        const int colbase = l16 * 8;
        float4 b0 = __ldg(&((const float4*)bias)[l16 * 2]);
        float4 b1 = __ldg(&((const float4*)bias)[l16 * 2 + 1]);
        float4 o0, o1;
        o0.x = fmaxf(fmaf(lo.x, inv, b0.x), 0.0f);
        o0.y = fmaxf(fmaf(lo.y, inv, b0.y), 0.0f);
        o0.z = fmaxf(fmaf(lo.z, inv, b0.z), 0.0f);
        o0.w = fmaxf(fmaf(lo.w, inv, b0.w), 0.0f);
        o1.x = fmaxf(fmaf(hi.x, inv, b1.x), 0.0f);
        o1.y = fmaxf(fmaf(hi.y, inv, b1.y), 0.0f);
        o1.z = fmaxf(fmaf(hi.z, inv, b1.z), 0.0f);
        o1.w = fmaxf(fmaf(hi.w, inv, b1.w), 0.0f);

        if (do_pool) {
            int g = __ldg(&batch[d]);
            red_add_v4(&g_pool[g * DH + colbase],     o0.x, o0.y, o0.z, o0.w);
            red_add_v4(&g_pool[g * DH + colbase + 4], o1.x, o1.y, o1.z, o1.w);
        } else {
            ((float4*)xout)[d * 32 + l16 * 2]     = o0;
            ((float4*)xout)[d * 32 + l16 * 2 + 1] = o1;
        }
    }
}

// ===========================================================================
// Classifier: one block (128 threads) per graph; pooled sums in g_pool.
// ===========================================================================
__global__ void __launch_bounds__(128) cls_kernel(
    const int* __restrict__ batch,
    const float* __restrict__ Wc1, const float* __restrict__ bc1,
    const float* __restrict__ Wc2, const float* __restrict__ bc2,
    const float* __restrict__ Wc3, const float* __restrict__ bc3,
    float* __restrict__ out)
{
    const int g = blockIdx.x;
    const int t = threadIdx.x;

    __shared__ int s_bounds[2];
    if (t < 2) {
        int target = g + t;
        int lo = 0, hi = NNODES;
        while (lo < hi) {
            int mid = (lo + hi) >> 1;
            if (__ldg(&batch[mid]) < target) lo = mid + 1;
            else hi = mid;
        }
        s_bounds[t] = lo;
    }
    __syncthreads();
    const float invc = 1.0f / fmaxf((float)(s_bounds[1] - s_bounds[0]), 1.0f);

    __shared__ float pooled[DH];
    __shared__ float z1s[CH];
    __shared__ float z2s[CH / 2];
    pooled[t] = g_pool[g * DH + t];
    __syncthreads();

    if (t < CH) {
        float a = 0.0f;
#pragma unroll 8
        for (int j = 0; j < DH; ++j)
            a += pooled[j] * __ldg(&Wc1[j * CH + t]);
        z1s[t] = fmaxf(fmaf(a, invc, __ldg(&bc1[t])), 0.0f);
    }
    __syncthreads();
    if (t < CH / 2) {
        float a = __ldg(&bc2[t]);
#pragma unroll
        for (int j = 0; j < CH; ++j)
            a += z1s[j] * __ldg(&Wc2[j * (CH / 2) + t]);
        z2s[t] = fmaxf(a, 0.0f);
    }
    __syncthreads();
    if (t < 2) {
        float a = __ldg(&bc3[t]);
#pragma unroll
        for (int j = 0; j < CH / 2; ++j)
            a += z2s[j] * __ldg(&Wc3[j * 2 + t]);
        out[g * 2 + t] = a;
    }
}

// ===========================================================================
// Launch. CSR build + pool zero forked onto a side stream.
// ===========================================================================
extern "C" void kernel_launch(void* const* d_in, const int* in_sizes, int n_in,
                              void* d_out, int out_size)
{
    const float* x     = (const float*)d_in[0];
    const int*   ei    = (const int*)  d_in[1];
    const int*   batch = (const int*)  d_in[2];
    const float* W1  = (const float*)d_in[3];
    const float* as1 = (const float*)d_in[4];
    const float* ad1 = (const float*)d_in[5];
    const float* b1  = (const float*)d_in[6];
    const float* W2  = (const float*)d_in[7];
    const float* as2 = (const float*)d_in[8];
    const float* ad2 = (const float*)d_in[9];
    const float* b2  = (const float*)d_in[10];
    const float* W3  = (const float*)d_in[11];
    const float* as3 = (const float*)d_in[12];
    const float* ad3 = (const float*)d_in[13];
    const float* b3  = (const float*)d_in[14];
    const float* Wc1 = (const float*)d_in[15];
    const float* bc1 = (const float*)d_in[16];
    const float* Wc2 = (const float*)d_in[17];
    const float* bc2 = (const float*)d_in[18];
    const float* Wc3 = (const float*)d_in[19];
    const float* bc3 = (const float*)d_in[20];

    const int* src = ei;
    const int* dst = ei + ETOT;

    const int tc_blocks = (NNODES + BM - 1) / BM;
    const int e_blocks  = (ETOT + 255) / 256;
    const int gw_blocks = (NNODES + 7) / 8;

    static cudaStream_t s_side = nullptr;
    static cudaEvent_t  ev_fork = nullptr, ev_join = nullptr;
    if (s_side == nullptr) {
        cudaStreamCreateWithFlags(&s_side, cudaStreamNonBlocking);
        cudaEventCreateWithFlags(&ev_fork, cudaEventDisableTiming);
        cudaEventCreateWithFlags(&ev_join, cudaEventDisableTiming);
    }

    // ---- fork: CSR build + pool zero on side stream ----
    cudaEventRecord(ev_fork, 0);
    cudaStreamWaitEvent(s_side, ev_fork, 0);
    init_kernel<<<(NNODES + 255) / 256, 256, 0, s_side>>>();
    fill_kernel<<<e_blocks, 256, 0, s_side>>>(src, dst);
    cudaEventRecord(ev_join, s_side);

    prep_kernel<<<(WTF_TOTAL + 255) / 256, 256>>>(W1, as1, ad1, W2, as2, ad2, W3, as3, ad3);
    gemm_alpha_tc<INCH><<<tc_blocks, 256>>>(x, 0, WTF_OFF1);

    cudaStreamWaitEvent(0, ev_join, 0);

    // ---- layer 1: -> bufA ----
    gat_gather_kernel<<<gw_blocks, 256>>>(1, b1, batch, 0);

    // ---- layer 2: bufA -> bufB ----
    gemm_alpha_tc<DH><<<tc_blocks, 256>>>(x, 1, WTF_OFF2);
    gat_gather_kernel<<<gw_blocks, 256>>>(2, b2, batch, 0);

    // ---- layer 3: bufB -> pooled directly ----
    gemm_alpha_tc<DH><<<tc_blocks, 256>>>(x, 2, WTF_OFF3);
    gat_gather_kernel<<<gw_blocks, 256>>>(1, b3, batch, 1);

    // ---- classifier ----
    cls_kernel<<<GG, 128>>>(batch, Wc1, bc1, Wc2, bc2, Wc3, bc3, (float*)d_out);
}

// round 17
// speedup vs baseline: 1.0338x; 1.0338x over previous
#include <cuda_runtime.h>
#include <cuda_fp16.h>
#include <cstdint>

// Problem constants (fixed by the reference).
#define NNODES 50000
#define ETOT   850000      // E (800000) + N self loops
#define GG     256
#define INCH   64
#define HEADS  8
#define CH     16
#define DH     128
#define NW     144         // DH + 8 (alpha_src) + 8 (alpha_dst)
#define NEG_SLOPE 0.2f
#define MAXDEG 64          // in-degree is Poisson(17); P(>63) ~ 1e-12
#define LOG2E 1.4426950408889634f

#define BM 64
#define BK 16
#define XS_STRIDE 20       // conflict-free a-frag loads
#define WS_STRIDE 152      // natural layout; b-frag scalar LDS conflict-free

#define WTF_OFF1 0
#define WTF_OFF2 (INCH * NW)
#define WTF_OFF3 (WTF_OFF2 + DH * NW)
#define WTF_TOTAL (WTF_OFF3 + DH * NW)
#define PI_TOTAL (WTF_TOTAL + NNODES + GG * DH)

// ---------------------------------------------------------------------------
// Scratch (__device__ globals; no allocations allowed).
// ---------------------------------------------------------------------------
__device__ __align__(128) uint32_t g_hh  [NNODES * (DH / 2)];  // h as half2
__device__ __align__(128) float    g_bufA[NNODES * DH];
__device__ __align__(128) float    g_bufB[NNODES * DH];
__device__ __align__(16)  float    g_asrc[NNODES * HEADS];
__device__ __align__(16)  float    g_adst[NNODES * HEADS];
__device__ __align__(128) uint32_t g_wtf [WTF_TOTAL];
__device__ __align__(128) float    g_pool[GG * DH];
__device__ int g_cnt [NNODES];
__device__ int g_csrc[NNODES * MAXDEG];

// ---------------------------------------------------------------------------
__device__ __forceinline__ float lrelu(float v) {
    return fmaxf(v, NEG_SLOPE * v);
}
__device__ __forceinline__ float* out_buf(int sel) { return sel == 1 ? g_bufA : g_bufB; }

__device__ __forceinline__ void red_add_v4(float* p, float a, float b, float c, float d) {
    asm volatile("red.global.add.v4.f32 [%0], {%1, %2, %3, %4};"
                 :: "l"(p), "f"(a), "f"(b), "f"(c), "f"(d) : "memory");
}

__device__ __forceinline__ uint32_t f2tf32(float f) {
    uint32_t r;
    asm("cvt.rna.tf32.f32 %0, %1;" : "=r"(r) : "f"(f));
    return r;
}

__device__ __forceinline__ uint32_t smem_u32(const void* p) {
    return (uint32_t)__cvta_generic_to_shared(p);
}

__device__ __forceinline__ void cp_async16(uint32_t dst, const void* src, int src_sz) {
    asm volatile("cp.async.ca.shared.global [%0], [%1], 16, %2;"
                 :: "r"(dst), "l"(src), "r"(src_sz));
}
__device__ __forceinline__ void cp_commit() {
    asm volatile("cp.async.commit_group;");
}
template <int N>
__device__ __forceinline__ void cp_wait() {
    asm volatile("cp.async.wait_group %0;" :: "n"(N));
}

__device__ __forceinline__ void mma_tf32(float* c,
                                         uint32_t a0, uint32_t a1, uint32_t a2, uint32_t a3,
                                         uint32_t b0, uint32_t b1)
{
    asm("mma.sync.aligned.m16n8k8.row.col.f32.tf32.tf32.f32 "
        "{%0,%1,%2,%3}, {%4,%5,%6,%7}, {%8,%9}, {%0,%1,%2,%3};"
        : "+f"(c[0]), "+f"(c[1]), "+f"(c[2]), "+f"(c[3])
        : "r"(a0), "r"(a1), "r"(a2), "r"(a3), "r"(b0), "r"(b1));
}

// ===========================================================================
// prep_init: fused tf32 weights [W|Wa_src|Wa_dst] (natural NW=144 layout,
// alpha cols pre-scaled by log2 e) + zero cnt + zero pool. One kernel.
// ===========================================================================
__global__ void prep_init_kernel(const float* __restrict__ W1, const float* __restrict__ as1, const float* __restrict__ ad1,
                                 const float* __restrict__ W2, const float* __restrict__ as2, const float* __restrict__ ad2,
                                 const float* __restrict__ W3, const float* __restrict__ as3, const float* __restrict__ ad3)
{
    int idx = blockIdx.x * blockDim.x + threadIdx.x;
    if (idx >= PI_TOTAL) return;

    if (idx >= WTF_TOTAL) {
        int j = idx - WTF_TOTAL;
        if (j < NNODES) g_cnt[j] = 0;
        else            g_pool[j - NNODES] = 0.0f;
        return;
    }

    const float *W, *as, *ad;
    int li;
    if (idx < WTF_OFF2)      { W = W1; as = as1; ad = ad1; li = idx - WTF_OFF1; }
    else if (idx < WTF_OFF3) { W = W2; as = as2; ad = ad2; li = idx - WTF_OFF2; }
    else                     { W = W3; as = as3; ad = ad3; li = idx - WTF_OFF3; }

    int k   = li / NW;
    int col = li - k * NW;

    float v;
    if (col < DH) {
        v = __ldg(&W[k * DH + col]);
    } else if (col < DH + HEADS) {
        int hh = col - DH;
        float s = 0.0f;
#pragma unroll
        for (int c = 0; c < CH; ++c)
            s += __ldg(&W[k * DH + hh * CH + c]) * __ldg(&as[hh * CH + c]);
        v = s * LOG2E;
    } else {
        int hh = col - DH - HEADS;
        float s = 0.0f;
#pragma unroll
        for (int c = 0; c < CH; ++c)
            s += __ldg(&W[k * DH + hh * CH + c]) * __ldg(&ad[hh * CH + c]);
        v = s * LOG2E;
    }
    g_wtf[idx] = f2tf32(v);
}

__global__ void fill_kernel(const int* __restrict__ src, const int* __restrict__ dst)
{
    int e = blockIdx.x * blockDim.x + threadIdx.x;
    if (e >= ETOT) return;
    int d = __ldg(&dst[e]);
    int pos = atomicAdd(&g_cnt[d], 1);
    if (pos < MAXDEG) g_csrc[d * MAXDEG + pos] = __ldg(&src[e]);
}

// ===========================================================================
// Node phase (tensor cores): [h | asrc | adst] = xin @ [W|Was|Wad]
// BM=64 rows, 8 warps: wr=wid&3 -> 16-row group, wg=wid>>2 -> 9 of 18 N-tiles.
// 9 accumulator frags/warp (~36 regs) -> 3 blocks/SM vs 2.
// h written as half2; alpha logits fp32.
// ===========================================================================
template <int K>
__global__ void __launch_bounds__(256) gemm_alpha_tc(const float* __restrict__ xext, int in_sel,
                                                     int wtf_off)
{
    const float* __restrict__ xin =
        (in_sel == 0) ? xext : (in_sel == 1 ? (const float*)g_bufA : (const float*)g_bufB);
    const uint32_t* __restrict__ wtf = g_wtf + wtf_off;

    __shared__ float    xs[2][BM][XS_STRIDE];
    __shared__ uint32_t ws[2][BK][WS_STRIDE];

    const int t    = threadIdx.x;            // 0..255
    const int wid  = t >> 5;                 // 0..7
    const int lid  = t & 31;
    const int wg   = wid >> 2;               // 0/1: N half
    const int wr   = wid & 3;                // 0..3: 16-row group
    const int row0 = blockIdx.x * BM;
    const int qr   = lid >> 2;               // 0..7
    const int qc   = lid & 3;                // 0..3
    const int nt0  = wg * 9;                 // first N-tile of this warp

    float c[9][4];
#pragma unroll
    for (int j = 0; j < 9; ++j)
#pragma unroll
        for (int e = 0; e < 4; ++e) c[j][e] = 0.0f;

    auto load_tiles = [&](int buf, int k0) {
        // xs: 64 rows x 16 floats = 256 float4; 1 per thread
        {
            int r   = t >> 2;
            int c4  = t & 3;
            int row = row0 + r;
            const float* src = &xin[(long)row * K + k0 + c4 * 4];
            int sz = (row < NNODES) ? 16 : 0;
            cp_async16(smem_u32(&xs[buf][r][c4 * 4]), src, sz);
        }
        // ws: 16 rows x 144 ints = 576 float4; <=3 per thread
#pragma unroll
        for (int i = 0; i < 3; ++i) {
            int idx = t + i * 256;
            if (idx < 576) {
                int r  = idx / 36;
                int c4 = idx - r * 36;
                cp_async16(smem_u32(&ws[buf][r][c4 * 4]), &wtf[(k0 + r) * NW + c4 * 4], 16);
            }
        }
    };

    load_tiles(0, 0);
    cp_commit();

    const int NK = K / BK;
    for (int kt = 0; kt < NK; ++kt) {
        const int buf = kt & 1;
        if (kt + 1 < NK) {
            load_tiles(buf ^ 1, (kt + 1) * BK);
            cp_commit();
            cp_wait<1>();
        } else {
            cp_wait<0>();
        }
        __syncthreads();

        const int r0 = wr * 16;
#pragma unroll
        for (int ks = 0; ks < BK; ks += 8) {
            uint32_t a0 = f2tf32(xs[buf][r0 + qr    ][ks + qc]);
            uint32_t a1 = f2tf32(xs[buf][r0 + qr + 8][ks + qc]);
            uint32_t a2 = f2tf32(xs[buf][r0 + qr    ][ks + qc + 4]);
            uint32_t a3 = f2tf32(xs[buf][r0 + qr + 8][ks + qc + 4]);

            const uint32_t* brow0 = &ws[buf][ks + qc    ][0];
            const uint32_t* brow1 = &ws[buf][ks + qc + 4][0];
#pragma unroll
            for (int j = 0; j < 9; ++j) {
                uint32_t b0 = brow0[(nt0 + j) * 8 + qr];
                uint32_t b1 = brow1[(nt0 + j) * 8 + qr];
                mma_tf32(c[j], a0, a1, a2, a3, b0, b1);
            }
        }
        __syncthreads();
    }

    // Direct fragment stores. Rows (wr*16+qr, +8); cols (nt)*8 + qc*2 + {0,1}.
    const int row1 = row0 + wr * 16 + qr;
    const int row2 = row1 + 8;
    const bool ok1 = row1 < NNODES;
    const bool ok2 = row2 < NNODES;

#pragma unroll
    for (int j = 0; j < 9; ++j) {
        int nt = nt0 + j;
        if (nt < 16) {
            int hidx = nt * 4 + qc;          // half2 index of col pair
            if (ok1) {
                half2 hv = __float22half2_rn(make_float2(c[j][0], c[j][1]));
                g_hh[row1 * (DH / 2) + hidx] = *(uint32_t*)&hv;
            }
            if (ok2) {
                half2 hv = __float22half2_rn(make_float2(c[j][2], c[j][3]));
                g_hh[row2 * (DH / 2) + hidx] = *(uint32_t*)&hv;
            }
        } else if (nt == 16) {
            int hh = qc * 2;
            if (ok1) *(float2*)&g_asrc[row1 * HEADS + hh] = make_float2(c[j][0], c[j][1]);
            if (ok2) *(float2*)&g_asrc[row2 * HEADS + hh] = make_float2(c[j][2], c[j][3]);
        } else {
            int hh = qc * 2;
            if (ok1) *(float2*)&g_adst[row1 * HEADS + hh] = make_float2(c[j][0], c[j][1]);
            if (ok2) *(float2*)&g_adst[row2 * HEADS + hh] = make_float2(c[j][2], c[j][3]);
        }
    }
}

// ===========================================================================
// Fused edge kernel (R12 version — best known). Warp per dst node; 16 lanes
// per edge (2 edges in parallel); lane owns 8 halfs (one uint4) of the row.
// ===========================================================================
__device__ __forceinline__ void acc8(float4& lo, float4& hi, const uint4& hv, float w)
{
    float2 f0 = __half22float2(*(const half2*)&hv.x);
    float2 f1 = __half22float2(*(const half2*)&hv.y);
    float2 f2 = __half22float2(*(const half2*)&hv.z);
    float2 f3 = __half22float2(*(const half2*)&hv.w);
    lo.x = fmaf(w, f0.x, lo.x); lo.y = fmaf(w, f0.y, lo.y);
    lo.z = fmaf(w, f1.x, lo.z); lo.w = fmaf(w, f1.y, lo.w);
    hi.x = fmaf(w, f2.x, hi.x); hi.y = fmaf(w, f2.y, hi.y);
    hi.z = fmaf(w, f3.x, hi.z); hi.w = fmaf(w, f3.y, hi.w);
}

__global__ void __launch_bounds__(256) gat_gather_kernel(int out_sel,
                                                         const float* __restrict__ bias,
                                                         const int* __restrict__ batch,
                                                         int do_pool)
{
    float* __restrict__ xout = out_buf(out_sel);
    const int lane = threadIdx.x & 31;
    const int d = blockIdx.x * (blockDim.x >> 5) + (threadIdx.x >> 5);
    if (d >= NNODES) return;

    const int half_id = lane >> 4;
    const int l16     = lane & 15;
    const int hh      = l16 >> 1;
    const int cnt     = __ldg(&g_cnt[d]);
    const int base    = d * MAXDEG;

    const float adc = __ldg(&g_adst[d * HEADS + hh]);

    int sv0 = 0, sv1 = 0;
    if (lane < cnt)      sv0 = __ldg(&g_csrc[base + lane]);
    if (lane + 32 < cnt) sv1 = __ldg(&g_csrc[base + lane + 32]);

    float sA = 0.0f, sB = 0.0f;
    float4 lo = make_float4(0.f, 0.f, 0.f, 0.f);
    float4 hi = make_float4(0.f, 0.f, 0.f, 0.f);
    const uint4* __restrict__ h8 = (const uint4*)g_hh;

    int i = 0;
    for (; i + 4 <= cnt; i += 4) {
        int j0 = i + half_id;
        int j1 = i + 2 + half_id;
        int a0 = __shfl_sync(0xffffffffu, sv0, j0 & 31);
        int b0 = __shfl_sync(0xffffffffu, sv1, j0 & 31);
        int a1 = __shfl_sync(0xffffffffu, sv0, j1 & 31);
        int b1 = __shfl_sync(0xffffffffu, sv1, j1 & 31);
        int s0 = (j0 < 32) ? a0 : b0;
        int s1 = (j1 < 32) ? a1 : b1;

        float as0 = __ldg(&g_asrc[s0 * HEADS + hh]);
        float as1 = __ldg(&g_asrc[s1 * HEADS + hh]);
        uint4 hv0 = __ldg(&h8[s0 * 16 + l16]);
        uint4 hv1 = __ldg(&h8[s1 * 16 + l16]);

        float w0 = exp2f(lrelu(as0 + adc));
        float w1 = exp2f(lrelu(as1 + adc));
        sA += w0;
        sB += w1;
        acc8(lo, hi, hv0, w0);
        acc8(lo, hi, hv1, w1);
    }
    for (; i < cnt; i += 2) {
        int j = i + half_id;
        bool valid = j < cnt;
        int jj = valid ? j : (cnt - 1);
        int a = __shfl_sync(0xffffffffu, sv0, jj & 31);
        int b = __shfl_sync(0xffffffffu, sv1, jj & 31);
        int s = (jj < 32) ? a : b;
        float as = __ldg(&g_asrc[s * HEADS + hh]);
        uint4 hv = __ldg(&h8[s * 16 + l16]);
        float w = valid ? exp2f(lrelu(as + adc)) : 0.0f;
        sA += w;
        acc8(lo, hi, hv, w);
    }

    float sT = sA + sB;
    sT  += __shfl_xor_sync(0xffffffffu, sT, 16);
    lo.x += __shfl_xor_sync(0xffffffffu, lo.x, 16);
    lo.y += __shfl_xor_sync(0xffffffffu, lo.y, 16);
    lo.z += __shfl_xor_sync(0xffffffffu, lo.z, 16);
    lo.w += __shfl_xor_sync(0xffffffffu, lo.w, 16);
    hi.x += __shfl_xor_sync(0xffffffffu, hi.x, 16);
    hi.y += __shfl_xor_sync(0xffffffffu, hi.y, 16);
    hi.z += __shfl_xor_sync(0xffffffffu, hi.z, 16);
    hi.w += __shfl_xor_sync(0xffffffffu, hi.w, 16);

    if (half_id == 0) {
        const float inv = 1.0f / sT;
        const int colbase = l16 * 8;
        float4 b0 = __ldg(&((const float4*)bias)[l16 * 2]);
        float4 b1 = __ldg(&((const float4*)bias)[l16 * 2 + 1]);
        float4 o0, o1;
        o0.x = fmaxf(fmaf(lo.x, inv, b0.x), 0.0f);
        o0.y = fmaxf(fmaf(lo.y, inv, b0.y), 0.0f);
        o0.z = fmaxf(fmaf(lo.z, inv, b0.z), 0.0f);
        o0.w = fmaxf(fmaf(lo.w, inv, b0.w), 0.0f);
        o1.x = fmaxf(fmaf(hi.x, inv, b1.x), 0.0f);
        o1.y = fmaxf(fmaf(hi.y, inv, b1.y), 0.0f);
        o1.z = fmaxf(fmaf(hi.z, inv, b1.z), 0.0f);
        o1.w = fmaxf(fmaf(hi.w, inv, b1.w), 0.0f);

        if (do_pool) {
            int g = __ldg(&batch[d]);
            red_add_v4(&g_pool[g * DH + colbase],     o0.x, o0.y, o0.z, o0.w);
            red_add_v4(&g_pool[g * DH + colbase + 4], o1.x, o1.y, o1.z, o1.w);
        } else {
            ((float4*)xout)[d * 32 + l16 * 2]     = o0;
            ((float4*)xout)[d * 32 + l16 * 2 + 1] = o1;
        }
    }
}

// ===========================================================================
// Classifier: one block (128 threads) per graph; pooled sums in g_pool.
// ===========================================================================
__global__ void __launch_bounds__(128) cls_kernel(
    const int* __restrict__ batch,
    const float* __restrict__ Wc1, const float* __restrict__ bc1,
    const float* __restrict__ Wc2, const float* __restrict__ bc2,
    const float* __restrict__ Wc3, const float* __restrict__ bc3,
    float* __restrict__ out)
{
    const int g = blockIdx.x;
    const int t = threadIdx.x;

    __shared__ int s_bounds[2];
    if (t < 2) {
        int target = g + t;
        int lo = 0, hi = NNODES;
        while (lo < hi) {
            int mid = (lo + hi) >> 1;
            if (__ldg(&batch[mid]) < target) lo = mid + 1;
            else hi = mid;
        }
        s_bounds[t] = lo;
    }
    __syncthreads();
    const float invc = 1.0f / fmaxf((float)(s_bounds[1] - s_bounds[0]), 1.0f);

    __shared__ float pooled[DH];
    __shared__ float z1s[CH];
    __shared__ float z2s[CH / 2];
    pooled[t] = g_pool[g * DH + t];
    __syncthreads();

    if (t < CH) {
        float a = 0.0f;
#pragma unroll 8
        for (int j = 0; j < DH; ++j)
            a += pooled[j] * __ldg(&Wc1[j * CH + t]);
        z1s[t] = fmaxf(fmaf(a, invc, __ldg(&bc1[t])), 0.0f);
    }
    __syncthreads();
    if (t < CH / 2) {
        float a = __ldg(&bc2[t]);
#pragma unroll
        for (int j = 0; j < CH; ++j)
            a += z1s[j] * __ldg(&Wc2[j * (CH / 2) + t]);
        z2s[t] = fmaxf(a, 0.0f);
    }
    __syncthreads();
    if (t < 2) {
        float a = __ldg(&bc3[t]);
#pragma unroll
        for (int j = 0; j < CH / 2; ++j)
            a += z2s[j] * __ldg(&Wc3[j * 2 + t]);
        out[g * 2 + t] = a;
    }
}

// ===========================================================================
// Launch. Order: prep_init(1), fill(2,side), gemm1(3), gather1(4), ...
// (gather is the 4th kernel launch -> lands in the ncu capture window)
// ===========================================================================
extern "C" void kernel_launch(void* const* d_in, const int* in_sizes, int n_in,
                              void* d_out, int out_size)
{
    const float* x     = (const float*)d_in[0];
    const int*   ei    = (const int*)  d_in[1];
    const int*   batch = (const int*)  d_in[2];
    const float* W1  = (const float*)d_in[3];
    const float* as1 = (const float*)d_in[4];
    const float* ad1 = (const float*)d_in[5];
    const float* b1  = (const float*)d_in[6];
    const float* W2  = (const float*)d_in[7];
    const float* as2 = (const float*)d_in[8];
    const float* ad2 = (const float*)d_in[9];
    const float* b2  = (const float*)d_in[10];
    const float* W3  = (const float*)d_in[11];
    const float* as3 = (const float*)d_in[12];
    const float* ad3 = (const float*)d_in[13];
    const float* b3  = (const float*)d_in[14];
    const float* Wc1 = (const float*)d_in[15];
    const float* bc1 = (const float*)d_in[16];
    const float* Wc2 = (const float*)d_in[17];
    const float* bc2 = (const float*)d_in[18];
    const float* Wc3 = (const float*)d_in[19];
    const float* bc3 = (const float*)d_in[20];

    const int* src = ei;
    const int* dst = ei + ETOT;

    const int tc_blocks = (NNODES + BM - 1) / BM;   // 782
    const int e_blocks  = (ETOT + 255) / 256;
    const int gw_blocks = (NNODES + 7) / 8;

    static cudaStream_t s_side = nullptr;
    static cudaEvent_t  ev_fork = nullptr, ev_join = nullptr;
    if (s_side == nullptr) {
        cudaStreamCreateWithFlags(&s_side, cudaStreamNonBlocking);
        cudaEventCreateWithFlags(&ev_fork, cudaEventDisableTiming);
        cudaEventCreateWithFlags(&ev_join, cudaEventDisableTiming);
    }

    // (1) prep weights + zero counters/pool (fill depends on it)
    prep_init_kernel<<<(PI_TOTAL + 255) / 256, 256>>>(W1, as1, ad1, W2, as2, ad2, W3, as3, ad3);

    // fork: (2) fill on side stream, overlapped with gemm1 on main
    cudaEventRecord(ev_fork, 0);
    cudaStreamWaitEvent(s_side, ev_fork, 0);
    fill_kernel<<<e_blocks, 256, 0, s_side>>>(src, dst);
    cudaEventRecord(ev_join, s_side);

    // (3) layer-1 GEMM
    gemm_alpha_tc<INCH><<<tc_blocks, 256>>>(x, 0, WTF_OFF1);

    // join before first gather
    cudaStreamWaitEvent(0, ev_join, 0);

    // (4) layer 1 gather: -> bufA
    gat_gather_kernel<<<gw_blocks, 256>>>(1, b1, batch, 0);

    // layer 2: bufA -> bufB
    gemm_alpha_tc<DH><<<tc_blocks, 256>>>(x, 1, WTF_OFF2);
    gat_gather_kernel<<<gw_blocks, 256>>>(2, b2, batch, 0);

    // layer 3: bufB -> pooled directly
    gemm_alpha_tc<DH><<<tc_blocks, 256>>>(x, 2, WTF_OFF3);
    gat_gather_kernel<<<gw_blocks, 256>>>(1, b3, batch, 1);

    // classifier
    cls_kernel<<<GG, 128>>>(batch, Wc1, bc1, Wc2, bc2, Wc3, bc3, (float*)d_out);
}